// round 15
// baseline (speedup 1.0000x reference)
#include <cuda_runtime.h>
#include <cuda_fp16.h>
#include <cstdint>
#include <math.h>

// ---------------------------------------------------------------------------
// lstm_30734785970219: z = [x|h] @ W (M=4096, K=2048, N=4096) + fused gates.
// R15: break the 128-reg ceiling WITHOUT losing warps: 3 CTAs x 128 threads
// (12 warps/SM, 170 regs/thread ceiling). Tile 128x64, warp tile 32x64 (same
// as best), 3-stage cp.async (24KB/stage, 74KB/CTA). Unrolled ks loop + reg
// slack lets ptxas software-pipeline LDSM under HMMA.
// fp16 mma.sync, fp32 accum, gate-interleaved N, fused fast-math epilogue.
// ---------------------------------------------------------------------------

static constexpr int MDIM = 4096;   // B*T
static constexpr int NDIM = 4096;   // 4*H (gate-interleaved)
static constexpr int KDIM = 2048;   // D_IN + H
static constexpr int HDIM = 1024;

static constexpr int BM = 128, BN = 64, BK = 64;
static constexpr int NCHUNK = KDIM / BK;                  // 32
static constexpr int STAGE_BYTES = (BM + BN) * BK * 2;    // 24 KB
static constexpr int B_OFF = BM * 128;                    // 16384
static constexpr int SMEM_BIAS = 3 * STAGE_BYTES;         // 73728
static constexpr int SMEM_TOTAL = SMEM_BIAS + 512;        // 74240 -> 3 CTAs/SM
static constexpr int ZSTRIDE = 68;                        // f32 row stride (pad)
static constexpr int ROWSTEP16 = 16 * KDIM;               // 16-row stride (elems)

static constexpr int PACKA_BLOCKS = MDIM * KDIM / 8 / 256;     // 4096
static constexpr int TRANS_BLOCKS_X = HDIM / 32;               // 32
static constexpr int TRANS_BLOCKS_Y = KDIM / 128;              // 16
static constexpr int PREP_BLOCKS = PACKA_BLOCKS + TRANS_BLOCKS_X * TRANS_BLOCKS_Y * 4;

// Scratch (allocation-free rule: __device__ globals)
__device__ __half g_A[(size_t)MDIM * KDIM];
__device__ __half g_Wt[(size_t)NDIM * KDIM];
__device__ __align__(16) float g_bias[NDIM];

// ---------------------------------------------------------------------------
// helpers
// ---------------------------------------------------------------------------
__device__ __forceinline__ uint32_t smem_to_u32(const void* p) {
    uint32_t a;
    asm("{ .reg .u64 t; cvta.to.shared.u64 t, %1; cvt.u32.u64 %0, t; }"
        : "=r"(a) : "l"(p));
    return a;
}

__device__ __forceinline__ void cp_async_16(uint32_t smem, const void* gmem) {
    asm volatile("cp.async.cg.shared.global [%0], [%1], 16;"
                 :: "r"(smem), "l"(gmem));
}
#define CP_COMMIT() asm volatile("cp.async.commit_group;" ::: "memory")
#define CP_WAIT(n)  asm volatile("cp.async.wait_group %0;" :: "n"(n) : "memory")

__device__ __forceinline__ void ldmatrix_x4(uint32_t& r0, uint32_t& r1,
                                            uint32_t& r2, uint32_t& r3,
                                            uint32_t addr) {
    asm volatile("ldmatrix.sync.aligned.m8n8.x4.shared.b16 {%0,%1,%2,%3}, [%4];"
                 : "=r"(r0), "=r"(r1), "=r"(r2), "=r"(r3) : "r"(addr));
}

__device__ __forceinline__ void mma_fp16(float* d, const uint32_t* a,
                                         uint32_t b0, uint32_t b1) {
    asm volatile(
        "mma.sync.aligned.m16n8k16.row.col.f32.f16.f16.f32 "
        "{%0,%1,%2,%3}, {%4,%5,%6,%7}, {%8,%9}, {%0,%1,%2,%3};"
        : "+f"(d[0]), "+f"(d[1]), "+f"(d[2]), "+f"(d[3])
        : "r"(a[0]), "r"(a[1]), "r"(a[2]), "r"(a[3]), "r"(b0), "r"(b1));
}

// Fast sigmoid / tanh (MUFU-based; saturate correctly at +/-inf).
__device__ __forceinline__ float fast_sigmoid(float x) {
    return __fdividef(1.0f, 1.0f + __expf(-x));
}
__device__ __forceinline__ float fast_tanh(float x) {
    return 1.0f - __fdividef(2.0f, __expf(2.0f * x) + 1.0f);
}

// ---------------------------------------------------------------------------
// Merged pre-pass kernel: blocks [0, 4096) pack A; rest transpose W + bias.
// ---------------------------------------------------------------------------
__global__ void prep_kernel(const float* __restrict__ x,
                            const float* __restrict__ h,
                            const float* __restrict__ Wf,
                            const float* __restrict__ Wi,
                            const float* __restrict__ Wg,
                            const float* __restrict__ Wo,
                            const float* __restrict__ bf,
                            const float* __restrict__ bi,
                            const float* __restrict__ bg,
                            const float* __restrict__ bo) {
    __shared__ float s[32][133];     // transpose staging (unused by pack-A)
    const int t = threadIdx.x;       // 256 threads

    if (blockIdx.x < PACKA_BLOCKS) {
        int idx = blockIdx.x * 256 + t;
        int m = idx >> 8;
        int k = (idx & 255) << 3;    // never straddles k=1024
        const float* src = (k < HDIM) ? (x + (size_t)m * HDIM + k)
                                      : (h + (size_t)m * HDIM + (k - HDIM));
        float4 v0 = *reinterpret_cast<const float4*>(src);
        float4 v1 = *reinterpret_cast<const float4*>(src + 4);
        __half2 o[4];
        o[0] = __floats2half2_rn(v0.x, v0.y);
        o[1] = __floats2half2_rn(v0.z, v0.w);
        o[2] = __floats2half2_rn(v1.x, v1.y);
        o[3] = __floats2half2_rn(v1.z, v1.w);
        *reinterpret_cast<uint4*>(g_A + (size_t)m * KDIM + k) =
            *reinterpret_cast<const uint4*>(o);
        return;
    }

    const int bb = blockIdx.x - PACKA_BLOCKS;            // 0..2047
    const int gate = bb >> 9;                            // /512
    const int rem = bb & 511;
    const int bx = rem & (TRANS_BLOCKS_X - 1);           // j tile (32)
    const int by = rem >> 5;                             // k tile (16)
    const float* W = (gate == 0) ? Wf : (gate == 1) ? Wi : (gate == 2) ? Wg : Wo;
    const int j0 = bx * 32;
    const int k0 = by * 128;

    const int jc = (t & 7) << 2;
    const int kr = t >> 3;
    #pragma unroll
    for (int it = 0; it < 4; ++it) {
        const int k = kr + it * 32;
        float4 v = *reinterpret_cast<const float4*>(
            W + (size_t)(k0 + k) * HDIM + j0 + jc);
        s[jc + 0][k] = v.x;
        s[jc + 1][k] = v.y;
        s[jc + 2][k] = v.z;
        s[jc + 3][k] = v.w;
    }
    __syncthreads();

    const int jj = t >> 3;
    const int kc = (t & 7) << 4;
    __half2 o[8];
    #pragma unroll
    for (int e = 0; e < 8; ++e)
        o[e] = __floats2half2_rn(s[jj][kc + 2 * e], s[jj][kc + 2 * e + 1]);
    __half* dst = g_Wt + (size_t)((j0 + jj) * 4 + gate) * KDIM + k0 + kc;
    reinterpret_cast<uint4*>(dst)[0] = reinterpret_cast<const uint4*>(o)[0];
    reinterpret_cast<uint4*>(dst)[1] = reinterpret_cast<const uint4*>(o)[1];

    if (by == 0 && t < 32) {
        const float* b = (gate == 0) ? bf : (gate == 1) ? bi
                        : (gate == 2) ? bg : bo;
        g_bias[(j0 + t) * 4 + gate] = b[j0 + t];
    }
}

// ---------------------------------------------------------------------------
// Main GEMM + fused LSTM epilogue (128 threads, 4 warps along M; BN=64)
// ---------------------------------------------------------------------------
__global__ __launch_bounds__(128, 3)
void lstm_gemm_kernel(const float* __restrict__ c_in, float* __restrict__ out) {
    extern __shared__ char smem[];
    const uint32_t smem_u32 = smem_to_u32(smem);
    const int tid = threadIdx.x;
    const int wid = tid >> 5;         // warp_m 0..3 -> 32 rows each
    const int lane = tid & 31;
    const int m0 = blockIdx.y * BM;
    const int r0 = blockIdx.x * BN;   // gate-interleaved column base
    const int jb = blockIdx.x * 16;   // hidden-unit base (16 units per CTA)

    float* bias_s = reinterpret_cast<float*>(smem + SMEM_BIAS);
    if (tid < 64) bias_s[tid] = g_bias[r0 + tid];

    // --- producers: 8 A rows + 4 B rows (16-row strides share swizzle) ----
    const int ci = tid & 7;           // 16B chunk in a 128B row
    const int crow = tid >> 3;        // row base (0..15)
    const uint32_t sw0 = (uint32_t)(crow * 128 + ((ci ^ (crow & 7)) << 4));
    const __half* pA0 = g_A  + (size_t)(m0 + crow) * KDIM + ci * 8;
    const __half* pB0 = g_Wt + (size_t)(r0 + crow) * KDIM + ci * 8;

    auto load_stage_adv = [&](uint32_t sm) {
        const uint32_t s0 = sm + sw0;
        #pragma unroll
        for (int rep = 0; rep < 8; ++rep)
            cp_async_16(s0 + rep * 2048, pA0 + (size_t)rep * ROWSTEP16);
        #pragma unroll
        for (int rep = 0; rep < 4; ++rep)
            cp_async_16(s0 + B_OFF + rep * 2048, pB0 + (size_t)rep * ROWSTEP16);
        pA0 += BK;
        pB0 += BK;
    };

    // prologue: stages 0,1 (groups #0, #1)
    load_stage_adv(smem_u32);
    CP_COMMIT();
    load_stage_adv(smem_u32 + STAGE_BYTES);
    CP_COMMIT();

    float acc[2][8][4];
    #pragma unroll
    for (int mt = 0; mt < 2; ++mt)
        #pragma unroll
        for (int nt = 0; nt < 8; ++nt)
            #pragma unroll
            for (int e = 0; e < 4; ++e) acc[mt][nt][e] = 0.0f;

    const int lrow = lane & 15;
    const int lhalf = lane >> 4;

    const int arow = wid * 32 + lrow;
    const uint32_t rA0 = (uint32_t)(arow * 128 + ((arow & 7) << 4));
    const uint32_t rB0 = (uint32_t)(B_OFF + lrow * 128 + ((lrow & 7) << 4));

    uint32_t scBase = smem_u32;                      // stage 0
    uint32_t spBase = smem_u32 + 2 * STAGE_BYTES;    // stage 2
    const uint32_t smTop = smem_u32 + 2 * STAGE_BYTES;

    #pragma unroll 1
    for (int c = 0; c < NCHUNK; ++c) {
        CP_WAIT(1);
        __syncthreads();
        if (c + 2 < NCHUNK)
            load_stage_adv(spBase);
        CP_COMMIT();

        const uint32_t aBase = scBase + rA0;
        const uint32_t bBase = scBase + rB0;

        #pragma unroll
        for (int ks = 0; ks < 4; ++ks) {
            const uint32_t cx = (uint32_t)((ks * 2 + lhalf) << 4);
            const uint32_t a0 = aBase ^ cx;
            const uint32_t b0 = bBase ^ cx;
            uint32_t a[2][4];
            ldmatrix_x4(a[0][0], a[0][1], a[0][2], a[0][3], a0);
            ldmatrix_x4(a[1][0], a[1][1], a[1][2], a[1][3], a0 + 2048);
            uint32_t b[4][4];
            ldmatrix_x4(b[0][0], b[0][1], b[0][2], b[0][3], b0);
            ldmatrix_x4(b[1][0], b[1][1], b[1][2], b[1][3], b0 + 2048);
            ldmatrix_x4(b[2][0], b[2][1], b[2][2], b[2][3], b0 + 4096);
            ldmatrix_x4(b[3][0], b[3][1], b[3][2], b[3][3], b0 + 6144);
            #pragma unroll
            for (int mt = 0; mt < 2; ++mt)
                #pragma unroll
                for (int nt = 0; nt < 8; ++nt)
                    mma_fp16(acc[mt][nt], a[mt],
                             b[nt >> 1][nt & 1], b[nt >> 1][(nt & 1) + 2]);
        }

        scBase = (scBase == smTop) ? smem_u32 : scBase + STAGE_BYTES;
        spBase = (spBase == smTop) ? smem_u32 : spBase + STAGE_BYTES;
    }

    // ---------------- epilogue: stage z through smem, fuse LSTM ----------------
    CP_WAIT(0);
    __syncthreads();
    float* zbuf = reinterpret_cast<float*>(smem);   // 128 x 68 f32 = 34.8 KB
    {
        const int rb = wid * 32 + (lane >> 2);
        const int cb = (lane & 3) * 2;
        #pragma unroll
        for (int mt = 0; mt < 2; ++mt)
            #pragma unroll
            for (int nt = 0; nt < 8; ++nt) {
                const int r = rb + mt * 16;
                const int cc = cb + nt * 8;
                zbuf[r * ZSTRIDE + cc]           = acc[mt][nt][0];
                zbuf[r * ZSTRIDE + cc + 1]       = acc[mt][nt][1];
                zbuf[(r + 8) * ZSTRIDE + cc]     = acc[mt][nt][2];
                zbuf[(r + 8) * ZSTRIDE + cc + 1] = acc[mt][nt][3];
            }
    }
    __syncthreads();

    {
        const int r = tid;                      // 0..127 local row
        const size_t m = (size_t)(m0 + r);
        const float* cin = c_in + m * HDIM + jb;
        float* hout = out + m * HDIM + jb;
        float* cout = out + (size_t)MDIM * HDIM + m * HDIM + jb;
        const float* zrow = zbuf + r * ZSTRIDE;

        #pragma unroll
        for (int q = 0; q < 4; ++q) {
            const int j0 = q * 4;               // 16 hidden units per thread
            float4 ci4 = *reinterpret_cast<const float4*>(cin + j0);
            const float* cip = &ci4.x;
            float hv[4], cv[4];
            #pragma unroll
            for (int e = 0; e < 4; ++e) {
                const int j = j0 + e;
                float4 z4 = *reinterpret_cast<const float4*>(zrow + j * 4);
                float4 b4 = *reinterpret_cast<const float4*>(bias_s + j * 4);
                float f = fast_sigmoid(z4.x + b4.x);
                float i = fast_sigmoid(z4.y + b4.y);
                float g = fast_tanh(z4.z + b4.z);
                float o = fast_sigmoid(z4.w + b4.w);
                float cval = f * cip[e] + g * i;
                cv[e] = cval;
                hv[e] = fast_tanh(cval) * o;
            }
            *reinterpret_cast<float4*>(hout + j0) =
                make_float4(hv[0], hv[1], hv[2], hv[3]);
            *reinterpret_cast<float4*>(cout + j0) =
                make_float4(cv[0], cv[1], cv[2], cv[3]);
        }
    }
}

// ---------------------------------------------------------------------------
// kernel_launch
// ---------------------------------------------------------------------------
extern "C" void kernel_launch(void* const* d_in, const int* in_sizes, int n_in,
                              void* d_out, int out_size) {
    const float* x    = (const float*)d_in[0];
    const float* h_in = (const float*)d_in[1];
    const float* c_in = (const float*)d_in[2];
    const float* Wf   = (const float*)d_in[3];
    const float* bf   = (const float*)d_in[4];
    const float* Wi   = (const float*)d_in[5];
    const float* bi   = (const float*)d_in[6];
    const float* Wg   = (const float*)d_in[7];
    const float* bg   = (const float*)d_in[8];
    const float* Wo   = (const float*)d_in[9];
    const float* bo   = (const float*)d_in[10];
    float* out = (float*)d_out;

    prep_kernel<<<PREP_BLOCKS, 256>>>(x, h_in, Wf, Wi, Wg, Wo, bf, bi, bg, bo);

    cudaFuncSetAttribute(lstm_gemm_kernel,
                         cudaFuncAttributeMaxDynamicSharedMemorySize, SMEM_TOTAL);
    lstm_gemm_kernel<<<dim3(NDIM / BN, MDIM / BM), 128, SMEM_TOTAL>>>(c_in, out);
}

// round 16
// speedup vs baseline: 1.0280x; 1.0280x over previous
#include <cuda_runtime.h>
#include <cuda_fp16.h>
#include <cstdint>
#include <math.h>

// ---------------------------------------------------------------------------
// lstm_30734785970219: z = [x|h] @ W (M=4096, K=2048, N=4096) + fused gates.
// R16: R14 loop (best, 219.0us) + PERSISTENT CTAs: 296 CTAs (2/SM x 148) pull
// tiles via an atomic ticket, eliminating the 4th partial wave (~13.5% of
// GEMM idle tail). fp16 mma.sync, fp32 accum, gate-interleaved N,
// fused fast-math LSTM epilogue. Counter reset in prep_kernel (stream order).
// ---------------------------------------------------------------------------

static constexpr int MDIM = 4096;   // B*T
static constexpr int NDIM = 4096;   // 4*H (gate-interleaved)
static constexpr int KDIM = 2048;   // D_IN + H
static constexpr int HDIM = 1024;

static constexpr int BM = 128, BN = 128, BK = 64;
static constexpr int NCHUNK = KDIM / BK;                  // 32
static constexpr int NTILES = (MDIM / BM) * (NDIM / BN);  // 1024
static constexpr int GEMM_CTAS = 296;                     // 2 per SM x 148
static constexpr int STAGE_BYTES = (BM + BN) * BK * 2;    // 32 KB
static constexpr int SMEM_BIAS = 3 * STAGE_BYTES;         // 98304
static constexpr int SMEM_TICKET = SMEM_BIAS + 512;       // 4B slot
static constexpr int SMEM_TOTAL = SMEM_TICKET + 16;       // 98836 -> 2 CTAs/SM
static constexpr int ZSTRIDE = 132;                       // f32 row stride (pad)
static constexpr int ROWSTEP = 32 * KDIM;                 // 32-row stride (elems)

static constexpr int PACKA_BLOCKS = MDIM * KDIM / 8 / 256;     // 4096
static constexpr int TRANS_BLOCKS_X = HDIM / 32;               // 32
static constexpr int TRANS_BLOCKS_Y = KDIM / 128;              // 16
static constexpr int PREP_BLOCKS = PACKA_BLOCKS + TRANS_BLOCKS_X * TRANS_BLOCKS_Y * 4;

// Scratch (allocation-free rule: __device__ globals)
__device__ __half g_A[(size_t)MDIM * KDIM];
__device__ __half g_Wt[(size_t)NDIM * KDIM];
__device__ __align__(16) float g_bias[NDIM];
__device__ int g_tile;

// ---------------------------------------------------------------------------
// helpers
// ---------------------------------------------------------------------------
__device__ __forceinline__ uint32_t smem_to_u32(const void* p) {
    uint32_t a;
    asm("{ .reg .u64 t; cvta.to.shared.u64 t, %1; cvt.u32.u64 %0, t; }"
        : "=r"(a) : "l"(p));
    return a;
}

__device__ __forceinline__ void cp_async_16(uint32_t smem, const void* gmem) {
    asm volatile("cp.async.cg.shared.global [%0], [%1], 16;"
                 :: "r"(smem), "l"(gmem));
}
#define CP_COMMIT() asm volatile("cp.async.commit_group;" ::: "memory")
#define CP_WAIT(n)  asm volatile("cp.async.wait_group %0;" :: "n"(n) : "memory")

__device__ __forceinline__ void ldmatrix_x4(uint32_t& r0, uint32_t& r1,
                                            uint32_t& r2, uint32_t& r3,
                                            uint32_t addr) {
    asm volatile("ldmatrix.sync.aligned.m8n8.x4.shared.b16 {%0,%1,%2,%3}, [%4];"
                 : "=r"(r0), "=r"(r1), "=r"(r2), "=r"(r3) : "r"(addr));
}

__device__ __forceinline__ void mma_fp16(float* d, const uint32_t* a,
                                         uint32_t b0, uint32_t b1) {
    asm volatile(
        "mma.sync.aligned.m16n8k16.row.col.f32.f16.f16.f32 "
        "{%0,%1,%2,%3}, {%4,%5,%6,%7}, {%8,%9}, {%0,%1,%2,%3};"
        : "+f"(d[0]), "+f"(d[1]), "+f"(d[2]), "+f"(d[3])
        : "r"(a[0]), "r"(a[1]), "r"(a[2]), "r"(a[3]), "r"(b0), "r"(b1));
}

// Fast sigmoid / tanh (MUFU-based; saturate correctly at +/-inf).
__device__ __forceinline__ float fast_sigmoid(float x) {
    return __fdividef(1.0f, 1.0f + __expf(-x));
}
__device__ __forceinline__ float fast_tanh(float x) {
    return 1.0f - __fdividef(2.0f, __expf(2.0f * x) + 1.0f);
}

// ---------------------------------------------------------------------------
// Merged pre-pass kernel: blocks [0, 4096) pack A; rest transpose W + bias.
// Block 0 also resets the persistent-tile counter (stream order vs GEMM).
// ---------------------------------------------------------------------------
__global__ void prep_kernel(const float* __restrict__ x,
                            const float* __restrict__ h,
                            const float* __restrict__ Wf,
                            const float* __restrict__ Wi,
                            const float* __restrict__ Wg,
                            const float* __restrict__ Wo,
                            const float* __restrict__ bf,
                            const float* __restrict__ bi,
                            const float* __restrict__ bg,
                            const float* __restrict__ bo) {
    __shared__ float s[32][133];     // transpose staging (unused by pack-A)
    const int t = threadIdx.x;       // 256 threads

    if (blockIdx.x == 0 && t == 0) g_tile = 0;

    if (blockIdx.x < PACKA_BLOCKS) {
        int idx = blockIdx.x * 256 + t;
        int m = idx >> 8;
        int k = (idx & 255) << 3;    // never straddles k=1024
        const float* src = (k < HDIM) ? (x + (size_t)m * HDIM + k)
                                      : (h + (size_t)m * HDIM + (k - HDIM));
        float4 v0 = *reinterpret_cast<const float4*>(src);
        float4 v1 = *reinterpret_cast<const float4*>(src + 4);
        __half2 o[4];
        o[0] = __floats2half2_rn(v0.x, v0.y);
        o[1] = __floats2half2_rn(v0.z, v0.w);
        o[2] = __floats2half2_rn(v1.x, v1.y);
        o[3] = __floats2half2_rn(v1.z, v1.w);
        *reinterpret_cast<uint4*>(g_A + (size_t)m * KDIM + k) =
            *reinterpret_cast<const uint4*>(o);
        return;
    }

    const int bb = blockIdx.x - PACKA_BLOCKS;            // 0..2047
    const int gate = bb >> 9;                            // /512
    const int rem = bb & 511;
    const int bx = rem & (TRANS_BLOCKS_X - 1);           // j tile (32)
    const int by = rem >> 5;                             // k tile (16)
    const float* W = (gate == 0) ? Wf : (gate == 1) ? Wi : (gate == 2) ? Wg : Wo;
    const int j0 = bx * 32;
    const int k0 = by * 128;

    const int jc = (t & 7) << 2;
    const int kr = t >> 3;
    #pragma unroll
    for (int it = 0; it < 4; ++it) {
        const int k = kr + it * 32;
        float4 v = *reinterpret_cast<const float4*>(
            W + (size_t)(k0 + k) * HDIM + j0 + jc);
        s[jc + 0][k] = v.x;
        s[jc + 1][k] = v.y;
        s[jc + 2][k] = v.z;
        s[jc + 3][k] = v.w;
    }
    __syncthreads();

    const int jj = t >> 3;
    const int kc = (t & 7) << 4;
    __half2 o[8];
    #pragma unroll
    for (int e = 0; e < 8; ++e)
        o[e] = __floats2half2_rn(s[jj][kc + 2 * e], s[jj][kc + 2 * e + 1]);
    __half* dst = g_Wt + (size_t)((j0 + jj) * 4 + gate) * KDIM + k0 + kc;
    reinterpret_cast<uint4*>(dst)[0] = reinterpret_cast<const uint4*>(o)[0];
    reinterpret_cast<uint4*>(dst)[1] = reinterpret_cast<const uint4*>(o)[1];

    if (by == 0 && t < 32) {
        const float* b = (gate == 0) ? bf : (gate == 1) ? bi
                        : (gate == 2) ? bg : bo;
        g_bias[(j0 + t) * 4 + gate] = b[j0 + t];
    }
}

// ---------------------------------------------------------------------------
// Persistent GEMM + fused LSTM epilogue (296 CTAs, 256 threads, 8 warps)
// Inner loop identical to R14.
// ---------------------------------------------------------------------------
__global__ __launch_bounds__(256, 2)
void lstm_gemm_kernel(const float* __restrict__ c_in, float* __restrict__ out) {
    extern __shared__ char smem[];
    const uint32_t smem_u32 = smem_to_u32(smem);
    const int tid = threadIdx.x;
    const int wid = tid >> 5;
    const int lane = tid & 31;
    const int warp_m = wid & 3;       // 0..3 -> 32 rows each
    const int warp_n = wid >> 2;      // 0..1 -> 64 cols each

    float* bias_s = reinterpret_cast<float*>(smem + SMEM_BIAS);
    int* tile_sh = reinterpret_cast<int*>(smem + SMEM_TICKET);
    float* zbuf = reinterpret_cast<float*>(smem);

    const int ci = tid & 7;           // 16B chunk in a 128B row
    const int crb = tid >> 3;         // row base (0..31)
    const uint32_t sw0 = (uint32_t)(crb * 128 + ((ci ^ (crb & 7)) << 4));

    const int lrow = lane & 15;
    const int lhalf = lane >> 4;
    const int arow = warp_m * 32 + lrow;
    const int brow = warp_n * 64 + lrow;
    const uint32_t rA0 = (uint32_t)(arow * 128 + ((arow & 7) << 4));
    const uint32_t rB0 = (uint32_t)(brow * 128 + ((brow & 7) << 4));
    const uint32_t smTop = smem_u32 + 2 * STAGE_BYTES;

    for (;;) {
        if (tid == 0) *tile_sh = atomicAdd(&g_tile, 1);
        __syncthreads();              // broadcast ticket; also protects zbuf
        const int tile = *tile_sh;
        if (tile >= NTILES) break;

        const int bx = tile & 31;     // N tile
        const int by = tile >> 5;     // M tile
        const int m0 = by * BM;
        const int r0 = bx * BN;       // gate-interleaved column base
        const int jb = bx * 32;       // hidden-unit base

        if (tid < 128) bias_s[tid] = g_bias[r0 + tid];

        const __half* pA0 = g_A  + (size_t)(m0 + crb) * KDIM + ci * 8;
        const __half* pB0 = g_Wt + (size_t)(r0 + crb) * KDIM + ci * 8;

        auto load_stage_adv = [&](uint32_t sm) {
            const uint32_t s0 = sm + sw0;
            #pragma unroll
            for (int rep = 0; rep < 4; ++rep)
                cp_async_16(s0 + rep * 4096, pA0 + rep * ROWSTEP);
            #pragma unroll
            for (int rep = 0; rep < 4; ++rep)
                cp_async_16(s0 + BM * 128 + rep * 4096, pB0 + rep * ROWSTEP);
            pA0 += BK;
            pB0 += BK;
        };

        // prologue: stages 0,1 (groups #0, #1)
        load_stage_adv(smem_u32);
        CP_COMMIT();
        load_stage_adv(smem_u32 + STAGE_BYTES);
        CP_COMMIT();

        float acc[2][8][4];
        #pragma unroll
        for (int mt = 0; mt < 2; ++mt)
            #pragma unroll
            for (int nt = 0; nt < 8; ++nt)
                #pragma unroll
                for (int e = 0; e < 4; ++e) acc[mt][nt][e] = 0.0f;

        uint32_t scBase = smem_u32;                      // stage 0
        uint32_t spBase = smem_u32 + 2 * STAGE_BYTES;    // stage 2

        #pragma unroll 1
        for (int c = 0; c < NCHUNK; ++c) {
            CP_WAIT(1);
            __syncthreads();
            if (c + 2 < NCHUNK)
                load_stage_adv(spBase);
            CP_COMMIT();

            const uint32_t aBase = scBase + rA0;
            const uint32_t bBase = scBase + BM * 128 + rB0;

            #pragma unroll
            for (int ks = 0; ks < 4; ++ks) {
                const uint32_t cx = (uint32_t)((ks * 2 + lhalf) << 4);
                const uint32_t a0 = aBase ^ cx;
                const uint32_t b0 = bBase ^ cx;
                uint32_t a[2][4];
                ldmatrix_x4(a[0][0], a[0][1], a[0][2], a[0][3], a0);
                ldmatrix_x4(a[1][0], a[1][1], a[1][2], a[1][3], a0 + 2048);
                uint32_t b[4][4];
                ldmatrix_x4(b[0][0], b[0][1], b[0][2], b[0][3], b0);
                ldmatrix_x4(b[1][0], b[1][1], b[1][2], b[1][3], b0 + 2048);
                ldmatrix_x4(b[2][0], b[2][1], b[2][2], b[2][3], b0 + 4096);
                ldmatrix_x4(b[3][0], b[3][1], b[3][2], b[3][3], b0 + 6144);
                #pragma unroll
                for (int mt = 0; mt < 2; ++mt)
                    #pragma unroll
                    for (int nt = 0; nt < 8; ++nt)
                        mma_fp16(acc[mt][nt], a[mt],
                                 b[nt >> 1][nt & 1], b[nt >> 1][(nt & 1) + 2]);
            }

            scBase = (scBase == smTop) ? smem_u32 : scBase + STAGE_BYTES;
            spBase = (spBase == smTop) ? smem_u32 : spBase + STAGE_BYTES;
        }

        // ------------- epilogue: stage z through smem, fuse LSTM -------------
        CP_WAIT(0);
        __syncthreads();
        {
            const int rb = warp_m * 32 + (lane >> 2);
            const int cb = warp_n * 64 + (lane & 3) * 2;
            #pragma unroll
            for (int mt = 0; mt < 2; ++mt)
                #pragma unroll
                for (int nt = 0; nt < 8; ++nt) {
                    const int r = rb + mt * 16;
                    const int cc = cb + nt * 8;
                    zbuf[r * ZSTRIDE + cc]           = acc[mt][nt][0];
                    zbuf[r * ZSTRIDE + cc + 1]       = acc[mt][nt][1];
                    zbuf[(r + 8) * ZSTRIDE + cc]     = acc[mt][nt][2];
                    zbuf[(r + 8) * ZSTRIDE + cc + 1] = acc[mt][nt][3];
                }
        }
        __syncthreads();

        {
            const int r = tid >> 1;                 // 0..127 local row
            const int jh = (tid & 1) * 16;          // 16 hidden units/thread
            const size_t m = (size_t)(m0 + r);
            const float* cin = c_in + m * HDIM + jb;
            float* hout = out + m * HDIM + jb;
            float* cout = out + (size_t)MDIM * HDIM + m * HDIM + jb;
            const float* zrow = zbuf + r * ZSTRIDE;

            #pragma unroll
            for (int q = 0; q < 4; ++q) {
                const int j0 = jh + q * 4;
                float4 ci4 = *reinterpret_cast<const float4*>(cin + j0);
                const float* cip = &ci4.x;
                float hv[4], cv[4];
                #pragma unroll
                for (int e = 0; e < 4; ++e) {
                    const int j = j0 + e;
                    float4 z4 = *reinterpret_cast<const float4*>(zrow + j * 4);
                    float4 b4 = *reinterpret_cast<const float4*>(bias_s + j * 4);
                    float f = fast_sigmoid(z4.x + b4.x);
                    float i = fast_sigmoid(z4.y + b4.y);
                    float g = fast_tanh(z4.z + b4.z);
                    float o = fast_sigmoid(z4.w + b4.w);
                    float cval = f * cip[e] + g * i;
                    cv[e] = cval;
                    hv[e] = fast_tanh(cval) * o;
                }
                *reinterpret_cast<float4*>(hout + j0) =
                    make_float4(hv[0], hv[1], hv[2], hv[3]);
                *reinterpret_cast<float4*>(cout + j0) =
                    make_float4(cv[0], cv[1], cv[2], cv[3]);
            }
        }
    }
}

// ---------------------------------------------------------------------------
// kernel_launch
// ---------------------------------------------------------------------------
extern "C" void kernel_launch(void* const* d_in, const int* in_sizes, int n_in,
                              void* d_out, int out_size) {
    const float* x    = (const float*)d_in[0];
    const float* h_in = (const float*)d_in[1];
    const float* c_in = (const float*)d_in[2];
    const float* Wf   = (const float*)d_in[3];
    const float* bf   = (const float*)d_in[4];
    const float* Wi   = (const float*)d_in[5];
    const float* bi   = (const float*)d_in[6];
    const float* Wg   = (const float*)d_in[7];
    const float* bg   = (const float*)d_in[8];
    const float* Wo   = (const float*)d_in[9];
    const float* bo   = (const float*)d_in[10];
    float* out = (float*)d_out;

    prep_kernel<<<PREP_BLOCKS, 256>>>(x, h_in, Wf, Wi, Wg, Wo, bf, bi, bg, bo);

    cudaFuncSetAttribute(lstm_gemm_kernel,
                         cudaFuncAttributeMaxDynamicSharedMemorySize, SMEM_TOTAL);
    lstm_gemm_kernel<<<GEMM_CTAS, 256, SMEM_TOTAL>>>(c_in, out);
}

// round 17
// speedup vs baseline: 1.0446x; 1.0162x over previous
#include <cuda_runtime.h>
#include <cuda_fp16.h>
#include <cstdint>
#include <math.h>

// ---------------------------------------------------------------------------
// lstm_30734785970219: z = [x|h] @ W (M=4096, K=2048, N=4096) + fused gates.
// R17: R16 (persistent tickets, best 217.2us) + periphery:
//  - epilogue store remap: lane pairs write contiguous 32B sectors (100%
//    sector efficiency on 64MB of h/c output; c_in reads too).
//  - pack_a: 16 floats/thread (MLP 4) for full DRAM latency hiding.
// GEMM mainloop byte-identical to R16. fp16 mma.sync, fp32 accum.
// ---------------------------------------------------------------------------

static constexpr int MDIM = 4096;   // B*T
static constexpr int NDIM = 4096;   // 4*H (gate-interleaved)
static constexpr int KDIM = 2048;   // D_IN + H
static constexpr int HDIM = 1024;

static constexpr int BM = 128, BN = 128, BK = 64;
static constexpr int NCHUNK = KDIM / BK;                  // 32
static constexpr int NTILES = (MDIM / BM) * (NDIM / BN);  // 1024
static constexpr int GEMM_CTAS = 296;                     // 2 per SM x 148
static constexpr int STAGE_BYTES = (BM + BN) * BK * 2;    // 32 KB
static constexpr int SMEM_BIAS = 3 * STAGE_BYTES;         // 98304
static constexpr int SMEM_TICKET = SMEM_BIAS + 512;       // 4B slot
static constexpr int SMEM_TOTAL = SMEM_TICKET + 16;       // 98836 -> 2 CTAs/SM
static constexpr int ZSTRIDE = 132;                       // f32 row stride (pad)
static constexpr int ROWSTEP = 32 * KDIM;                 // 32-row stride (elems)

static constexpr int PACKA_BLOCKS = MDIM * KDIM / 16 / 256;    // 2048
static constexpr int TRANS_BLOCKS_X = HDIM / 32;               // 32
static constexpr int TRANS_BLOCKS_Y = KDIM / 128;              // 16
static constexpr int PREP_BLOCKS = PACKA_BLOCKS + TRANS_BLOCKS_X * TRANS_BLOCKS_Y * 4;

// Scratch (allocation-free rule: __device__ globals)
__device__ __half g_A[(size_t)MDIM * KDIM];
__device__ __half g_Wt[(size_t)NDIM * KDIM];
__device__ __align__(16) float g_bias[NDIM];
__device__ int g_tile;

// ---------------------------------------------------------------------------
// helpers
// ---------------------------------------------------------------------------
__device__ __forceinline__ uint32_t smem_to_u32(const void* p) {
    uint32_t a;
    asm("{ .reg .u64 t; cvta.to.shared.u64 t, %1; cvt.u32.u64 %0, t; }"
        : "=r"(a) : "l"(p));
    return a;
}

__device__ __forceinline__ void cp_async_16(uint32_t smem, const void* gmem) {
    asm volatile("cp.async.cg.shared.global [%0], [%1], 16;"
                 :: "r"(smem), "l"(gmem));
}
#define CP_COMMIT() asm volatile("cp.async.commit_group;" ::: "memory")
#define CP_WAIT(n)  asm volatile("cp.async.wait_group %0;" :: "n"(n) : "memory")

__device__ __forceinline__ void ldmatrix_x4(uint32_t& r0, uint32_t& r1,
                                            uint32_t& r2, uint32_t& r3,
                                            uint32_t addr) {
    asm volatile("ldmatrix.sync.aligned.m8n8.x4.shared.b16 {%0,%1,%2,%3}, [%4];"
                 : "=r"(r0), "=r"(r1), "=r"(r2), "=r"(r3) : "r"(addr));
}

__device__ __forceinline__ void mma_fp16(float* d, const uint32_t* a,
                                         uint32_t b0, uint32_t b1) {
    asm volatile(
        "mma.sync.aligned.m16n8k16.row.col.f32.f16.f16.f32 "
        "{%0,%1,%2,%3}, {%4,%5,%6,%7}, {%8,%9}, {%0,%1,%2,%3};"
        : "+f"(d[0]), "+f"(d[1]), "+f"(d[2]), "+f"(d[3])
        : "r"(a[0]), "r"(a[1]), "r"(a[2]), "r"(a[3]), "r"(b0), "r"(b1));
}

// Fast sigmoid / tanh (MUFU-based; saturate correctly at +/-inf).
__device__ __forceinline__ float fast_sigmoid(float x) {
    return __fdividef(1.0f, 1.0f + __expf(-x));
}
__device__ __forceinline__ float fast_tanh(float x) {
    return 1.0f - __fdividef(2.0f, __expf(2.0f * x) + 1.0f);
}

// ---------------------------------------------------------------------------
// Merged pre-pass kernel: blocks [0, 2048) pack A; rest transpose W + bias.
// Block 0 also resets the persistent-tile counter (stream order vs GEMM).
// ---------------------------------------------------------------------------
__global__ void prep_kernel(const float* __restrict__ x,
                            const float* __restrict__ h,
                            const float* __restrict__ Wf,
                            const float* __restrict__ Wi,
                            const float* __restrict__ Wg,
                            const float* __restrict__ Wo,
                            const float* __restrict__ bf,
                            const float* __restrict__ bi,
                            const float* __restrict__ bg,
                            const float* __restrict__ bo) {
    __shared__ float s[32][133];     // transpose staging (unused by pack-A)
    const int t = threadIdx.x;       // 256 threads

    if (blockIdx.x == 0 && t == 0) g_tile = 0;

    if (blockIdx.x < PACKA_BLOCKS) {
        // 16 floats per thread (4 independent float4 loads -> MLP 4).
        int idx = blockIdx.x * 256 + t;
        int m = idx >> 7;
        int k = (idx & 127) << 4;    // 16-float chunks never straddle k=1024
        const float* src = (k < HDIM) ? (x + (size_t)m * HDIM + k)
                                      : (h + (size_t)m * HDIM + (k - HDIM));
        float4 v0 = *reinterpret_cast<const float4*>(src);
        float4 v1 = *reinterpret_cast<const float4*>(src + 4);
        float4 v2 = *reinterpret_cast<const float4*>(src + 8);
        float4 v3 = *reinterpret_cast<const float4*>(src + 12);
        __half2 o[8];
        o[0] = __floats2half2_rn(v0.x, v0.y);
        o[1] = __floats2half2_rn(v0.z, v0.w);
        o[2] = __floats2half2_rn(v1.x, v1.y);
        o[3] = __floats2half2_rn(v1.z, v1.w);
        o[4] = __floats2half2_rn(v2.x, v2.y);
        o[5] = __floats2half2_rn(v2.z, v2.w);
        o[6] = __floats2half2_rn(v3.x, v3.y);
        o[7] = __floats2half2_rn(v3.z, v3.w);
        uint4* dst = reinterpret_cast<uint4*>(g_A + (size_t)m * KDIM + k);
        dst[0] = reinterpret_cast<const uint4*>(o)[0];
        dst[1] = reinterpret_cast<const uint4*>(o)[1];
        return;
    }

    const int bb = blockIdx.x - PACKA_BLOCKS;            // 0..2047
    const int gate = bb >> 9;                            // /512
    const int rem = bb & 511;
    const int bx = rem & (TRANS_BLOCKS_X - 1);           // j tile (32)
    const int by = rem >> 5;                             // k tile (16)
    const float* W = (gate == 0) ? Wf : (gate == 1) ? Wi : (gate == 2) ? Wg : Wo;
    const int j0 = bx * 32;
    const int k0 = by * 128;

    const int jc = (t & 7) << 2;
    const int kr = t >> 3;
    #pragma unroll
    for (int it = 0; it < 4; ++it) {
        const int k = kr + it * 32;
        float4 v = *reinterpret_cast<const float4*>(
            W + (size_t)(k0 + k) * HDIM + j0 + jc);
        s[jc + 0][k] = v.x;
        s[jc + 1][k] = v.y;
        s[jc + 2][k] = v.z;
        s[jc + 3][k] = v.w;
    }
    __syncthreads();

    const int jj = t >> 3;
    const int kc = (t & 7) << 4;
    __half2 o[8];
    #pragma unroll
    for (int e = 0; e < 8; ++e)
        o[e] = __floats2half2_rn(s[jj][kc + 2 * e], s[jj][kc + 2 * e + 1]);
    __half* dst = g_Wt + (size_t)((j0 + jj) * 4 + gate) * KDIM + k0 + kc;
    reinterpret_cast<uint4*>(dst)[0] = reinterpret_cast<const uint4*>(o)[0];
    reinterpret_cast<uint4*>(dst)[1] = reinterpret_cast<const uint4*>(o)[1];

    if (by == 0 && t < 32) {
        const float* b = (gate == 0) ? bf : (gate == 1) ? bi
                        : (gate == 2) ? bg : bo;
        g_bias[(j0 + t) * 4 + gate] = b[j0 + t];
    }
}

// ---------------------------------------------------------------------------
// Persistent GEMM + fused LSTM epilogue (296 CTAs, 256 threads, 8 warps)
// Mainloop identical to R16.
// ---------------------------------------------------------------------------
__global__ __launch_bounds__(256, 2)
void lstm_gemm_kernel(const float* __restrict__ c_in, float* __restrict__ out) {
    extern __shared__ char smem[];
    const uint32_t smem_u32 = smem_to_u32(smem);
    const int tid = threadIdx.x;
    const int wid = tid >> 5;
    const int lane = tid & 31;
    const int warp_m = wid & 3;       // 0..3 -> 32 rows each
    const int warp_n = wid >> 2;      // 0..1 -> 64 cols each

    float* bias_s = reinterpret_cast<float*>(smem + SMEM_BIAS);
    int* tile_sh = reinterpret_cast<int*>(smem + SMEM_TICKET);
    float* zbuf = reinterpret_cast<float*>(smem);

    const int ci = tid & 7;           // 16B chunk in a 128B row
    const int crb = tid >> 3;         // row base (0..31)
    const uint32_t sw0 = (uint32_t)(crb * 128 + ((ci ^ (crb & 7)) << 4));

    const int lrow = lane & 15;
    const int lhalf = lane >> 4;
    const int arow = warp_m * 32 + lrow;
    const int brow = warp_n * 64 + lrow;
    const uint32_t rA0 = (uint32_t)(arow * 128 + ((arow & 7) << 4));
    const uint32_t rB0 = (uint32_t)(brow * 128 + ((brow & 7) << 4));
    const uint32_t smTop = smem_u32 + 2 * STAGE_BYTES;

    for (;;) {
        if (tid == 0) *tile_sh = atomicAdd(&g_tile, 1);
        __syncthreads();              // broadcast ticket; also protects zbuf
        const int tile = *tile_sh;
        if (tile >= NTILES) break;

        const int bx = tile & 31;     // N tile
        const int by = tile >> 5;     // M tile
        const int m0 = by * BM;
        const int r0 = bx * BN;       // gate-interleaved column base
        const int jb = bx * 32;       // hidden-unit base

        if (tid < 128) bias_s[tid] = g_bias[r0 + tid];

        const __half* pA0 = g_A  + (size_t)(m0 + crb) * KDIM + ci * 8;
        const __half* pB0 = g_Wt + (size_t)(r0 + crb) * KDIM + ci * 8;

        auto load_stage_adv = [&](uint32_t sm) {
            const uint32_t s0 = sm + sw0;
            #pragma unroll
            for (int rep = 0; rep < 4; ++rep)
                cp_async_16(s0 + rep * 4096, pA0 + rep * ROWSTEP);
            #pragma unroll
            for (int rep = 0; rep < 4; ++rep)
                cp_async_16(s0 + BM * 128 + rep * 4096, pB0 + rep * ROWSTEP);
            pA0 += BK;
            pB0 += BK;
        };

        // prologue: stages 0,1 (groups #0, #1)
        load_stage_adv(smem_u32);
        CP_COMMIT();
        load_stage_adv(smem_u32 + STAGE_BYTES);
        CP_COMMIT();

        float acc[2][8][4];
        #pragma unroll
        for (int mt = 0; mt < 2; ++mt)
            #pragma unroll
            for (int nt = 0; nt < 8; ++nt)
                #pragma unroll
                for (int e = 0; e < 4; ++e) acc[mt][nt][e] = 0.0f;

        uint32_t scBase = smem_u32;                      // stage 0
        uint32_t spBase = smem_u32 + 2 * STAGE_BYTES;    // stage 2

        #pragma unroll 1
        for (int c = 0; c < NCHUNK; ++c) {
            CP_WAIT(1);
            __syncthreads();
            if (c + 2 < NCHUNK)
                load_stage_adv(spBase);
            CP_COMMIT();

            const uint32_t aBase = scBase + rA0;
            const uint32_t bBase = scBase + BM * 128 + rB0;

            #pragma unroll
            for (int ks = 0; ks < 4; ++ks) {
                const uint32_t cx = (uint32_t)((ks * 2 + lhalf) << 4);
                const uint32_t a0 = aBase ^ cx;
                const uint32_t b0 = bBase ^ cx;
                uint32_t a[2][4];
                ldmatrix_x4(a[0][0], a[0][1], a[0][2], a[0][3], a0);
                ldmatrix_x4(a[1][0], a[1][1], a[1][2], a[1][3], a0 + 2048);
                uint32_t b[4][4];
                ldmatrix_x4(b[0][0], b[0][1], b[0][2], b[0][3], b0);
                ldmatrix_x4(b[1][0], b[1][1], b[1][2], b[1][3], b0 + 2048);
                ldmatrix_x4(b[2][0], b[2][1], b[2][2], b[2][3], b0 + 4096);
                ldmatrix_x4(b[3][0], b[3][1], b[3][2], b[3][3], b0 + 6144);
                #pragma unroll
                for (int mt = 0; mt < 2; ++mt)
                    #pragma unroll
                    for (int nt = 0; nt < 8; ++nt)
                        mma_fp16(acc[mt][nt], a[mt],
                                 b[nt >> 1][nt & 1], b[nt >> 1][(nt & 1) + 2]);
            }

            scBase = (scBase == smTop) ? smem_u32 : scBase + STAGE_BYTES;
            spBase = (spBase == smTop) ? smem_u32 : spBase + STAGE_BYTES;
        }

        // ------------- epilogue: stage z through smem, fuse LSTM -------------
        CP_WAIT(0);
        __syncthreads();
        {
            const int rb = warp_m * 32 + (lane >> 2);
            const int cb = warp_n * 64 + (lane & 3) * 2;
            #pragma unroll
            for (int mt = 0; mt < 2; ++mt)
                #pragma unroll
                for (int nt = 0; nt < 8; ++nt) {
                    const int r = rb + mt * 16;
                    const int cc = cb + nt * 8;
                    zbuf[r * ZSTRIDE + cc]           = acc[mt][nt][0];
                    zbuf[r * ZSTRIDE + cc + 1]       = acc[mt][nt][1];
                    zbuf[(r + 8) * ZSTRIDE + cc]     = acc[mt][nt][2];
                    zbuf[(r + 8) * ZSTRIDE + cc + 1] = acc[mt][nt][3];
                }
        }
        __syncthreads();

        {
            // Lane pairs (2i, 2i+1) cover contiguous 32B: j0 = jo + q*8.
            const int r = tid >> 1;                 // 0..127 local row
            const int jo = (tid & 1) * 4;
            const size_t m = (size_t)(m0 + r);
            const float* cin = c_in + m * HDIM + jb;
            float* hout = out + m * HDIM + jb;
            float* cout = out + (size_t)MDIM * HDIM + m * HDIM + jb;
            const float* zrow = zbuf + r * ZSTRIDE;

            #pragma unroll
            for (int q = 0; q < 4; ++q) {
                const int j0 = jo + q * 8;          // 16 hidden units/thread
                float4 ci4 = *reinterpret_cast<const float4*>(cin + j0);
                const float* cip = &ci4.x;
                float hv[4], cv[4];
                #pragma unroll
                for (int e = 0; e < 4; ++e) {
                    const int j = j0 + e;
                    float4 z4 = *reinterpret_cast<const float4*>(zrow + j * 4);
                    float4 b4 = *reinterpret_cast<const float4*>(bias_s + j * 4);
                    float f = fast_sigmoid(z4.x + b4.x);
                    float i = fast_sigmoid(z4.y + b4.y);
                    float g = fast_tanh(z4.z + b4.z);
                    float o = fast_sigmoid(z4.w + b4.w);
                    float cval = f * cip[e] + g * i;
                    cv[e] = cval;
                    hv[e] = fast_tanh(cval) * o;
                }
                *reinterpret_cast<float4*>(hout + j0) =
                    make_float4(hv[0], hv[1], hv[2], hv[3]);
                *reinterpret_cast<float4*>(cout + j0) =
                    make_float4(cv[0], cv[1], cv[2], cv[3]);
            }
        }
    }
}

// ---------------------------------------------------------------------------
// kernel_launch
// ---------------------------------------------------------------------------
extern "C" void kernel_launch(void* const* d_in, const int* in_sizes, int n_in,
                              void* d_out, int out_size) {
    const float* x    = (const float*)d_in[0];
    const float* h_in = (const float*)d_in[1];
    const float* c_in = (const float*)d_in[2];
    const float* Wf   = (const float*)d_in[3];
    const float* bf   = (const float*)d_in[4];
    const float* Wi   = (const float*)d_in[5];
    const float* bi   = (const float*)d_in[6];
    const float* Wg   = (const float*)d_in[7];
    const float* bg   = (const float*)d_in[8];
    const float* Wo   = (const float*)d_in[9];
    const float* bo   = (const float*)d_in[10];
    float* out = (float*)d_out;

    prep_kernel<<<PREP_BLOCKS, 256>>>(x, h_in, Wf, Wi, Wg, Wo, bf, bi, bg, bo);

    cudaFuncSetAttribute(lstm_gemm_kernel,
                         cudaFuncAttributeMaxDynamicSharedMemorySize, SMEM_TOTAL);
    lstm_gemm_kernel<<<GEMM_CTAS, 256, SMEM_TOTAL>>>(c_in, out);
}